// round 7
// baseline (speedup 1.0000x reference)
#include <cuda_runtime.h>
#include <math.h>

// ChannelDropout:
//   kept[b,c]  = ||positions[b,c] - center|| > 0.2
//   proba[b,c] = mean_i( ||positions[b,c] - mc_centers[i]|| > 0.2 )
//   out[b,c,t] = brain_sig[b,c,t] * kept / (1e-8 + proba)
//
// One block per (b,c) row. Minimum-overhead variant:
//   - 3 float4 loads per thread front-batched (HBM stream starts first)
//   - scale computed by WARP 0 only (__reduce_add_sync, no atomics)
//   - exactly ONE __syncthreads, hidden under the in-flight DRAM loads
//   - plain LDG/STG (measured faster than .cs streaming hints in R3)

#define DROPOUT_R 0.2f
#define EPS_V     1e-8f

__device__ __forceinline__ bool dist_gt(float px, float py, float qx, float qy) {
    // Match jnp.linalg.norm(...) > 0.2 bit-for-bit: unfused mul/add + exact sqrt.
    float dx = px - qx;
    float dy = py - qy;
    float d2 = __fadd_rn(__fmul_rn(dx, dx), __fmul_rn(dy, dy));
    return sqrtf(d2) > DROPOUT_R;
}

__global__ void __launch_bounds__(256)
channel_dropout_kernel(const float* __restrict__ sig,
                       const float* __restrict__ pos,
                       const float* __restrict__ center,
                       const float* __restrict__ mc,
                       float* __restrict__ out,
                       int T, int n_mc)
{
    const int row  = blockIdx.x;
    const int tid  = threadIdx.x;

    __shared__ float s_scale;

    const int T4 = T >> 2;                       // float4 count (T=3000 -> 750)
    const float4* __restrict__ src = reinterpret_cast<const float4*>(sig) + (size_t)row * T4;
    float4*       __restrict__ dst = reinterpret_cast<float4*>(out)       + (size_t)row * T4;

    // Front-batch the row loads: the whole block's HBM read stream is in
    // flight before any scale work or synchronization happens.
    const int i0 = tid;
    const int i1 = tid + 256;
    const int i2 = tid + 512;
    const bool p0 = i0 < T4, p1 = i1 < T4, p2 = i2 < T4;
    float4 v0, v1, v2;
    if (p0) v0 = src[i0];
    if (p1) v1 = src[i1];
    if (p2) v2 = src[i2];

    // Warp 0 computes the row scale while everyone else's loads are in
    // flight. 100 MC tests split 32-wide -> REDUX -> one STS.
    if (tid < 32) {
        const float2 p = __ldg(reinterpret_cast<const float2*>(pos) + row);
        const float2* __restrict__ mc2 = reinterpret_cast<const float2*>(mc);

        int local = 0;
        for (int i = tid; i < n_mc; i += 32) {
            float2 c = __ldg(&mc2[i]);
            if (dist_gt(p.x, p.y, c.x, c.y)) local++;
        }
        const int cnt = __reduce_add_sync(0xffffffffu, local);

        if (tid == 0) {
            bool  kept  = dist_gt(p.x, p.y, __ldg(&center[0]), __ldg(&center[1]));
            float proba = (float)cnt / (float)n_mc;
            s_scale = kept ? (1.0f / (EPS_V + proba)) : 0.0f;
        }
    }
    __syncthreads();

    const float sc = s_scale;

    if (p0) { v0.x *= sc; v0.y *= sc; v0.z *= sc; v0.w *= sc; dst[i0] = v0; }
    if (p1) { v1.x *= sc; v1.y *= sc; v1.z *= sc; v1.w *= sc; dst[i1] = v1; }
    if (p2) { v2.x *= sc; v2.y *= sc; v2.z *= sc; v2.w *= sc; dst[i2] = v2; }

    // Generic continuation if T4 > 768 (not hit for T=3000).
    for (int i = tid + 768; i < T4; i += 256) {
        float4 v = src[i];
        v.x *= sc; v.y *= sc; v.z *= sc; v.w *= sc;
        dst[i] = v;
    }

    // Scalar tail if T not divisible by 4 (not hit for T=3000).
    const int tail = T4 << 2;
    const float* srow = sig + (size_t)row * T;
    float*       drow = out + (size_t)row * T;
    for (int t = tail + tid; t < T; t += 256) {
        drow[t] = srow[t] * sc;
    }
}

extern "C" void kernel_launch(void* const* d_in, const int* in_sizes, int n_in,
                              void* d_out, int out_size)
{
    const float* sig    = (const float*)d_in[0];   // brain_sig  (B*C*T)
    const float* pos    = (const float*)d_in[1];   // positions  (B*C*2)
    const float* center = (const float*)d_in[2];   // center     (2)
    const float* mc     = (const float*)d_in[3];   // mc_centers (N*2)
    float*       out    = (float*)d_out;

    const int rows = in_sizes[1] / 2;              // B*C = 17472
    const int T    = in_sizes[0] / rows;           // 3000
    const int n_mc = in_sizes[3] / 2;              // 100

    channel_dropout_kernel<<<rows, 256>>>(sig, pos, center, mc, out, T, n_mc);
}